// round 2
// baseline (speedup 1.0000x reference)
#include <cuda_runtime.h>
#include <math.h>

#define D_    256
#define H_    8
#define HD_   32
#define MAXT_ 16384

// Scratch (static device globals — allocation-free, within harness rules)
__device__ float g_h[(size_t)MAXT_ * D_];        // LayerNorm output      [T,256]
__device__ float g_qkv[(size_t)MAXT_ * 3 * D_];  // fused qkv projection  [T,768]
__device__ float g_ao[(size_t)MAXT_ * D_];       // attention output      [T,256]
__device__ int   g_offs[64];                     // canonical int32 batch offsets

// ---------------------------------------------------------------------------
// Kernel 0: canonicalize batch_offsets. The reference creates int64 offsets
// but jnp.asarray (x64 disabled) downcasts to int32 — we cannot trust the
// dtype. Detect: int64 layout has raw[1]==0 (high word of offset 0 is word 1,
// first nonzero offset 512 starts at word 2); int32 layout has raw[1]==512.
// ---------------------------------------------------------------------------
__global__ void conv_offs_kernel(const int* __restrict__ raw, int n) {
    if (threadIdx.x == 0) {
        bool is64 = (raw[1] == 0);
        for (int i = 0; i < n; i++)
            g_offs[i] = is64 ? raw[2 * i] : raw[i];
    }
}

// ---------------------------------------------------------------------------
// Kernel 1: LayerNorm. One warp per token (256 features = 8 per lane).
// ---------------------------------------------------------------------------
__global__ void ln_kernel(const float* __restrict__ x,
                          const float* __restrict__ gamma,
                          const float* __restrict__ beta, int T) {
    int t = blockIdx.x * blockDim.y + threadIdx.y;
    if (t >= T) return;
    int lane = threadIdx.x;
    const float* row = x + (size_t)t * D_;
    float v[8];
    float sum = 0.f, sq = 0.f;
#pragma unroll
    for (int i = 0; i < 8; i++) {
        v[i] = row[lane + i * 32];
        sum += v[i];
        sq  += v[i] * v[i];
    }
#pragma unroll
    for (int o = 16; o > 0; o >>= 1) {
        sum += __shfl_xor_sync(0xffffffffu, sum, o);
        sq  += __shfl_xor_sync(0xffffffffu, sq, o);
    }
    float mu  = sum * (1.0f / D_);
    float var = sq * (1.0f / D_) - mu * mu;
    float rs  = rsqrtf(var + 1e-5f);
    float* out = g_h + (size_t)t * D_;
#pragma unroll
    for (int i = 0; i < 8; i++) {
        int c = lane + i * 32;
        out[c] = (v[i] - mu) * rs * gamma[c] + beta[c];
    }
}

// ---------------------------------------------------------------------------
// Kernel 2/4: SGEMM  C[M,N] = A[M,K] @ W[N,K]^T + bias (+ residual).
// BM=128, BN=64, BK=32, 256 threads, 8x4 microtile. Transposed smem tiles
// with +4 padding.
// ---------------------------------------------------------------------------
template<bool RES>
__global__ __launch_bounds__(256)
void gemm_kernel(const float* __restrict__ A, const float* __restrict__ W,
                 const float* __restrict__ bias, const float* __restrict__ res,
                 float* __restrict__ C, int M, int N, int K) {
    constexpr int BM = 128, BN = 64, BK = 32, TM = 8, TN = 4;
    __shared__ float As[BK][BM + 4];
    __shared__ float Ws[BK][BN + 4];
    const int tid = threadIdx.x;
    const int tx  = tid & 15;   // 0..15 -> n
    const int ty  = tid >> 4;   // 0..15 -> m
    const int m0  = blockIdx.y * BM;
    const int n0  = blockIdx.x * BN;

    float acc[TM][TN];
#pragma unroll
    for (int i = 0; i < TM; i++)
#pragma unroll
        for (int j = 0; j < TN; j++) acc[i][j] = 0.f;

    for (int k0 = 0; k0 < K; k0 += BK) {
        // A tile: 128x32 floats -> 2 float4 per thread, stored transposed
#pragma unroll
        for (int p = 0; p < (BM * BK) / (256 * 4); p++) {
            int idx = tid + p * 256;
            int r   = idx >> 3;       // 0..127 (row within tile)
            int c4  = idx & 7;        // float4 column
            int gr  = m0 + r;
            float4 val = make_float4(0.f, 0.f, 0.f, 0.f);
            if (gr < M)
                val = *(const float4*)(A + (size_t)gr * K + k0 + c4 * 4);
            As[c4 * 4 + 0][r] = val.x;
            As[c4 * 4 + 1][r] = val.y;
            As[c4 * 4 + 2][r] = val.z;
            As[c4 * 4 + 3][r] = val.w;
        }
        // W tile: 64x32 floats -> 1 float4 per thread (N is multiple of 64)
#pragma unroll
        for (int p = 0; p < (BN * BK) / (256 * 4); p++) {
            int idx = tid + p * 256;
            int r   = idx >> 3;
            int c4  = idx & 7;
            float4 val = *(const float4*)(W + (size_t)(n0 + r) * K + k0 + c4 * 4);
            Ws[c4 * 4 + 0][r] = val.x;
            Ws[c4 * 4 + 1][r] = val.y;
            Ws[c4 * 4 + 2][r] = val.z;
            Ws[c4 * 4 + 3][r] = val.w;
        }
        __syncthreads();
#pragma unroll
        for (int k = 0; k < BK; k++) {
            float a[TM], b[TN];
#pragma unroll
            for (int i = 0; i < TM / 4; i++) {
                float4 t4 = *(const float4*)&As[k][ty * TM + i * 4];
                a[i * 4 + 0] = t4.x; a[i * 4 + 1] = t4.y;
                a[i * 4 + 2] = t4.z; a[i * 4 + 3] = t4.w;
            }
            {
                float4 t4 = *(const float4*)&Ws[k][tx * TN];
                b[0] = t4.x; b[1] = t4.y; b[2] = t4.z; b[3] = t4.w;
            }
#pragma unroll
            for (int i = 0; i < TM; i++)
#pragma unroll
                for (int j = 0; j < TN; j++)
                    acc[i][j] = fmaf(a[i], b[j], acc[i][j]);
        }
        __syncthreads();
    }

    // Epilogue: bias (+ residual) then vectorized store
#pragma unroll
    for (int i = 0; i < TM; i++) {
        int row = m0 + ty * TM + i;
        if (row >= M) continue;
        int col = n0 + tx * TN;
        float4 out;
        out.x = acc[i][0] + bias[col + 0];
        out.y = acc[i][1] + bias[col + 1];
        out.z = acc[i][2] + bias[col + 2];
        out.w = acc[i][3] + bias[col + 3];
        if (RES) {
            float4 rr = *(const float4*)(res + (size_t)row * N + col);
            out.x += rr.x; out.y += rr.y; out.z += rr.z; out.w += rr.w;
        }
        *(float4*)(C + (size_t)row * N + col) = out;
    }
}

// ---------------------------------------------------------------------------
// Kernel 3: ragged flash attention. Block = (128 queries, 1 head, 1 seq),
// one query per thread. K/V tiles of 32 rows in smem; compute-side smem
// reads are same-address broadcasts. Online softmax, masking via -inf.
// ---------------------------------------------------------------------------
__global__ __launch_bounds__(128)
void attn_kernel() {
    const int b = blockIdx.z;
    const int h = blockIdx.y;
    const int off = g_offs[b];
    const int len = g_offs[b + 1] - off;
    const int q0  = blockIdx.x * 128;
    if (q0 >= len) return;

    const int tq = q0 + threadIdx.x;
    const bool valid = tq < len;
    const float scale = 0.17677669529663687f;  // 1/sqrt(32)
    const float NEG_INF = -INFINITY;

    float q[HD_];
    {
        const float* qrow = g_qkv + (size_t)(off + (valid ? tq : q0)) * (3 * D_) + h * HD_;
#pragma unroll
        for (int d = 0; d < HD_; d++) q[d] = valid ? qrow[d] * scale : 0.f;
    }
    float o[HD_];
#pragma unroll
    for (int d = 0; d < HD_; d++) o[d] = 0.f;
    float m = NEG_INF, l = 0.f;

    __shared__ float Ks[32][HD_];
    __shared__ float Vs[32][HD_];

    for (int k0 = 0; k0 < len; k0 += 32) {
        const int jn = min(32, len - k0);
        // load K/V tile: 2 x (32x32) floats, float4 per thread, zero-fill tail
#pragma unroll
        for (int p = 0; p < 2; p++) {
            int fi = threadIdx.x + p * 128;
            int j  = fi >> 3;
            int d4 = fi & 7;
            float4 kv = make_float4(0.f, 0.f, 0.f, 0.f);
            float4 vv = make_float4(0.f, 0.f, 0.f, 0.f);
            if (j < jn) {
                const float* base =
                    g_qkv + (size_t)(off + k0 + j) * (3 * D_) + h * HD_ + d4 * 4;
                kv = *(const float4*)(base + D_);       // K part
                vv = *(const float4*)(base + 2 * D_);   // V part
            }
            *(float4*)&Ks[j][d4 * 4] = kv;
            *(float4*)&Vs[j][d4 * 4] = vv;
        }
        __syncthreads();

        float s[32];
#pragma unroll
        for (int j = 0; j < 32; j++) {
            float acc = 0.f;
#pragma unroll
            for (int d4 = 0; d4 < 8; d4++) {
                float4 kv = *(const float4*)&Ks[j][d4 * 4];   // broadcast LDS
                acc = fmaf(q[d4 * 4 + 0], kv.x, acc);
                acc = fmaf(q[d4 * 4 + 1], kv.y, acc);
                acc = fmaf(q[d4 * 4 + 2], kv.z, acc);
                acc = fmaf(q[d4 * 4 + 3], kv.w, acc);
            }
            s[j] = acc;
        }

        float tmax = NEG_INF;
#pragma unroll
        for (int j = 0; j < 32; j++) {
            if (j >= jn) s[j] = NEG_INF;
            tmax = fmaxf(tmax, s[j]);
        }
        float mnew  = fmaxf(m, tmax);
        float alpha = __expf(m - mnew);   // exp(-inf)=0 on first tile
        l *= alpha;
#pragma unroll
        for (int d = 0; d < HD_; d++) o[d] *= alpha;

#pragma unroll
        for (int j = 0; j < 32; j++) {
            float p = __expf(s[j] - mnew);   // masked entries -> 0
            l += p;
#pragma unroll
            for (int d4 = 0; d4 < 8; d4++) {
                float4 vv = *(const float4*)&Vs[j][d4 * 4];   // broadcast LDS
                o[d4 * 4 + 0] = fmaf(p, vv.x, o[d4 * 4 + 0]);
                o[d4 * 4 + 1] = fmaf(p, vv.y, o[d4 * 4 + 1]);
                o[d4 * 4 + 2] = fmaf(p, vv.z, o[d4 * 4 + 2]);
                o[d4 * 4 + 3] = fmaf(p, vv.w, o[d4 * 4 + 3]);
            }
        }
        m = mnew;
        __syncthreads();
    }

    if (valid) {
        float inv = 1.0f / l;
        float* orow = g_ao + (size_t)(off + tq) * D_ + h * HD_;
#pragma unroll
        for (int d = 0; d < HD_; d++) orow[d] = o[d] * inv;
    }
}

// ---------------------------------------------------------------------------
// Launch: offsets -> LN -> QKV GEMM -> attention -> out-proj(+residual).
// All stream-ordered, graph-capturable, allocation-free.
// ---------------------------------------------------------------------------
extern "C" void kernel_launch(void* const* d_in, const int* in_sizes, int n_in,
                              void* d_out, int out_size) {
    const float* x     = (const float*)d_in[0];
    const float* in_w  = (const float*)d_in[1];
    const float* in_b  = (const float*)d_in[2];
    const float* out_w = (const float*)d_in[3];
    const float* out_b = (const float*)d_in[4];
    const float* gamma = (const float*)d_in[5];
    const float* beta  = (const float*)d_in[6];
    const int*   offs  = (const int*)d_in[7];   // int32 OR int64 — detected on device

    const int T = in_sizes[0] / D_;          // 12137
    const int B = in_sizes[7] - 1;           // 16

    void *ph, *pq, *po;
    cudaGetSymbolAddress(&ph, g_h);
    cudaGetSymbolAddress(&pq, g_qkv);
    cudaGetSymbolAddress(&po, g_ao);
    float* h_ptr = (float*)ph;
    float* qkv   = (float*)pq;
    float* ao    = (float*)po;

    // Canonicalize offsets (dtype-robust)
    conv_offs_kernel<<<1, 32>>>(offs, B + 1);

    {   // LayerNorm
        dim3 blk(32, 8);
        ln_kernel<<<(T + 7) / 8, blk>>>(x, gamma, beta, T);
    }
    {   // QKV projection: [T,256] x [768,256]^T
        dim3 grid((3 * D_) / 64, (T + 127) / 128);
        gemm_kernel<false><<<grid, 256>>>(h_ptr, in_w, in_b, nullptr, qkv,
                                          T, 3 * D_, D_);
    }
    {   // Ragged flash attention
        dim3 grid(8 /* ceil(1024/128) q-tiles */, H_, B);
        attn_kernel<<<grid, 128>>>();
    }
    {   // Output projection + residual: [T,256] x [256,256]^T + x
        dim3 grid(D_ / 64, (T + 127) / 128);
        gemm_kernel<true><<<grid, 256>>>(ao, out_w, out_b, x, (float*)d_out,
                                         T, D_, D_);
    }
}

// round 3
// speedup vs baseline: 1.4732x; 1.4732x over previous
#include <cuda_runtime.h>
#include <math.h>
#include <stdint.h>

#define D_    256
#define H_    8
#define HD_   32
#define MAXT_ 16384

// Scratch (static device globals — allocation-free, within harness rules)
__device__ float g_h[(size_t)MAXT_ * D_];        // LayerNorm output      [T,256]
__device__ float g_qkv[(size_t)MAXT_ * 3 * D_];  // fused qkv projection  [T,768]
__device__ float g_ao[(size_t)MAXT_ * D_];       // attention output      [T,256]
__device__ int   g_offs[64];                     // canonical int32 batch offsets

// ---------------------------------------------------------------------------
// tf32 warp-MMA helpers
// ---------------------------------------------------------------------------
__device__ __forceinline__ uint32_t f2tf32(float x) {
    uint32_t r;
    asm("cvt.rna.tf32.f32 %0, %1;" : "=r"(r) : "f"(x));
    return r;
}

__device__ __forceinline__ void mma_tf32(float c[4], const uint32_t a[4],
                                         const uint32_t b[2]) {
    asm volatile(
        "mma.sync.aligned.m16n8k8.row.col.f32.tf32.tf32.f32 "
        "{%0,%1,%2,%3}, {%4,%5,%6,%7}, {%8,%9}, {%0,%1,%2,%3};\n"
        : "+f"(c[0]), "+f"(c[1]), "+f"(c[2]), "+f"(c[3])
        : "r"(a[0]), "r"(a[1]), "r"(a[2]), "r"(a[3]), "r"(b[0]), "r"(b[1]));
}

// ---------------------------------------------------------------------------
// Kernel 0: canonicalize batch_offsets (int32 or int64 — auto-detect).
// ---------------------------------------------------------------------------
__global__ void conv_offs_kernel(const int* __restrict__ raw, int n) {
    if (threadIdx.x == 0) {
        bool is64 = (raw[1] == 0);
        for (int i = 0; i < n; i++)
            g_offs[i] = is64 ? raw[2 * i] : raw[i];
    }
}

// ---------------------------------------------------------------------------
// Kernel 1: LayerNorm. One warp per token.
// ---------------------------------------------------------------------------
__global__ void ln_kernel(const float* __restrict__ x,
                          const float* __restrict__ gamma,
                          const float* __restrict__ beta, int T) {
    int t = blockIdx.x * blockDim.y + threadIdx.y;
    if (t >= T) return;
    int lane = threadIdx.x;
    const float* row = x + (size_t)t * D_;
    float v[8];
    float sum = 0.f, sq = 0.f;
#pragma unroll
    for (int i = 0; i < 8; i++) {
        v[i] = row[lane + i * 32];
        sum += v[i];
        sq  += v[i] * v[i];
    }
#pragma unroll
    for (int o = 16; o > 0; o >>= 1) {
        sum += __shfl_xor_sync(0xffffffffu, sum, o);
        sq  += __shfl_xor_sync(0xffffffffu, sq, o);
    }
    float mu  = sum * (1.0f / D_);
    float var = sq * (1.0f / D_) - mu * mu;
    float rs  = rsqrtf(var + 1e-5f);
    float* out = g_h + (size_t)t * D_;
#pragma unroll
    for (int i = 0; i < 8; i++) {
        int c = lane + i * 32;
        out[c] = (v[i] - mu) * rs * gamma[c] + beta[c];
    }
}

// ---------------------------------------------------------------------------
// Kernel 2/4: SGEMM  C[M,N] = A[M,K] @ W[N,K]^T + bias (+ residual).
// ---------------------------------------------------------------------------
template<bool RES>
__global__ __launch_bounds__(256)
void gemm_kernel(const float* __restrict__ A, const float* __restrict__ W,
                 const float* __restrict__ bias, const float* __restrict__ res,
                 float* __restrict__ C, int M, int N, int K) {
    constexpr int BM = 128, BN = 64, BK = 32, TM = 8, TN = 4;
    __shared__ float As[BK][BM + 4];
    __shared__ float Ws[BK][BN + 4];
    const int tid = threadIdx.x;
    const int tx  = tid & 15;
    const int ty  = tid >> 4;
    const int m0  = blockIdx.y * BM;
    const int n0  = blockIdx.x * BN;

    float acc[TM][TN];
#pragma unroll
    for (int i = 0; i < TM; i++)
#pragma unroll
        for (int j = 0; j < TN; j++) acc[i][j] = 0.f;

    for (int k0 = 0; k0 < K; k0 += BK) {
#pragma unroll
        for (int p = 0; p < (BM * BK) / (256 * 4); p++) {
            int idx = tid + p * 256;
            int r   = idx >> 3;
            int c4  = idx & 7;
            int gr  = m0 + r;
            float4 val = make_float4(0.f, 0.f, 0.f, 0.f);
            if (gr < M)
                val = *(const float4*)(A + (size_t)gr * K + k0 + c4 * 4);
            As[c4 * 4 + 0][r] = val.x;
            As[c4 * 4 + 1][r] = val.y;
            As[c4 * 4 + 2][r] = val.z;
            As[c4 * 4 + 3][r] = val.w;
        }
#pragma unroll
        for (int p = 0; p < (BN * BK) / (256 * 4); p++) {
            int idx = tid + p * 256;
            int r   = idx >> 3;
            int c4  = idx & 7;
            float4 val = *(const float4*)(W + (size_t)(n0 + r) * K + k0 + c4 * 4);
            Ws[c4 * 4 + 0][r] = val.x;
            Ws[c4 * 4 + 1][r] = val.y;
            Ws[c4 * 4 + 2][r] = val.z;
            Ws[c4 * 4 + 3][r] = val.w;
        }
        __syncthreads();
#pragma unroll
        for (int k = 0; k < BK; k++) {
            float a[TM], b[TN];
#pragma unroll
            for (int i = 0; i < TM / 4; i++) {
                float4 t4 = *(const float4*)&As[k][ty * TM + i * 4];
                a[i * 4 + 0] = t4.x; a[i * 4 + 1] = t4.y;
                a[i * 4 + 2] = t4.z; a[i * 4 + 3] = t4.w;
            }
            {
                float4 t4 = *(const float4*)&Ws[k][tx * TN];
                b[0] = t4.x; b[1] = t4.y; b[2] = t4.z; b[3] = t4.w;
            }
#pragma unroll
            for (int i = 0; i < TM; i++)
#pragma unroll
                for (int j = 0; j < TN; j++)
                    acc[i][j] = fmaf(a[i], b[j], acc[i][j]);
        }
        __syncthreads();
    }

#pragma unroll
    for (int i = 0; i < TM; i++) {
        int row = m0 + ty * TM + i;
        if (row >= M) continue;
        int col = n0 + tx * TN;
        float4 out;
        out.x = acc[i][0] + bias[col + 0];
        out.y = acc[i][1] + bias[col + 1];
        out.z = acc[i][2] + bias[col + 2];
        out.w = acc[i][3] + bias[col + 3];
        if (RES) {
            float4 rr = *(const float4*)(res + (size_t)row * N + col);
            out.x += rr.x; out.y += rr.y; out.z += rr.z; out.w += rr.w;
        }
        *(float4*)(C + (size_t)row * N + col) = out;
    }
}

// ---------------------------------------------------------------------------
// Kernel 3: tf32 mma.sync flash attention.
// Block = 4 warps = 64 queries for one (batch, head). Warp owns 16 queries.
// Key tiles of 32 in smem (pre-converted tf32, padded rows).
// S = Q·K^T via m16n8k8; online softmax in C-fragment layout (quad shfls);
// P permuted C->A layout via shfls; O += P·V via m16n8k8.
// ---------------------------------------------------------------------------
__global__ __launch_bounds__(128)
void attn_mma_kernel() {
    const int b = blockIdx.z;
    const int h = blockIdx.y;
    const int off = g_offs[b];
    const int len = g_offs[b + 1] - off;
    const int q0  = blockIdx.x * 64;
    if (q0 >= len) return;

    const int warp = threadIdx.x >> 5;
    const int lane = threadIdx.x & 31;
    const int tg   = lane & 3;    // thread-in-quad (col group)
    const int grp  = lane >> 2;   // quad id (row)
    const int qw   = q0 + warp * 16;

    const float scale = 0.17677669529663687f;  // 1/sqrt(32)
    const float NEG_INF = -INFINITY;

    __shared__ uint32_t Ks[32][33];  // tf32 bits, +1 pad
    __shared__ uint32_t Vs[32][33];

    // --- Q fragments (row-major A, 4 k-chunks of 8) ---
    uint32_t qa[4][4];
    {
        const int r0 = qw + grp;
        const int r1 = r0 + 8;
        const float* base = g_qkv + (size_t)off * (3 * D_) + h * HD_;
#pragma unroll
        for (int kc = 0; kc < 4; kc++) {
            int d0 = kc * 8 + tg, d1 = d0 + 4;
            float v00 = (r0 < len) ? base[(size_t)r0 * (3 * D_) + d0] * scale : 0.f;
            float v10 = (r1 < len) ? base[(size_t)r1 * (3 * D_) + d0] * scale : 0.f;
            float v01 = (r0 < len) ? base[(size_t)r0 * (3 * D_) + d1] * scale : 0.f;
            float v11 = (r1 < len) ? base[(size_t)r1 * (3 * D_) + d1] * scale : 0.f;
            qa[kc][0] = f2tf32(v00);
            qa[kc][1] = f2tf32(v10);
            qa[kc][2] = f2tf32(v01);
            qa[kc][3] = f2tf32(v11);
        }
    }

    float o[4][4];
#pragma unroll
    for (int dt = 0; dt < 4; dt++)
#pragma unroll
        for (int i = 0; i < 4; i++) o[dt][i] = 0.f;
    float m0 = NEG_INF, m1 = NEG_INF, l0 = 0.f, l1 = 0.f;

    for (int k0 = 0; k0 < len; k0 += 32) {
        // --- cooperative K/V tile load: 32 keys x 32 dims, cvt to tf32 ---
#pragma unroll
        for (int p = 0; p < 2; p++) {
            int idx = threadIdx.x + p * 128;   // 0..255 float4 slots
            int key = idx >> 3;                // 0..31
            int d4  = (idx & 7) * 4;
            float4 kv = make_float4(0.f, 0.f, 0.f, 0.f);
            float4 vv = make_float4(0.f, 0.f, 0.f, 0.f);
            if (k0 + key < len) {
                const float* src =
                    g_qkv + (size_t)(off + k0 + key) * (3 * D_) + h * HD_ + d4;
                kv = *(const float4*)(src + D_);       // K
                vv = *(const float4*)(src + 2 * D_);   // V
            }
            Ks[key][d4 + 0] = f2tf32(kv.x);
            Ks[key][d4 + 1] = f2tf32(kv.y);
            Ks[key][d4 + 2] = f2tf32(kv.z);
            Ks[key][d4 + 3] = f2tf32(kv.w);
            Vs[key][d4 + 0] = f2tf32(vv.x);
            Vs[key][d4 + 1] = f2tf32(vv.y);
            Vs[key][d4 + 2] = f2tf32(vv.z);
            Vs[key][d4 + 3] = f2tf32(vv.w);
        }
        __syncthreads();

        // --- S = Q K^T : 4 n-tiles of 8 keys, 4 k-chunks of 8 dims ---
        float s[4][4];
#pragma unroll
        for (int nt = 0; nt < 4; nt++) {
            s[nt][0] = s[nt][1] = s[nt][2] = s[nt][3] = 0.f;
#pragma unroll
            for (int kc = 0; kc < 4; kc++) {
                uint32_t bb[2];
                bb[0] = Ks[nt * 8 + grp][kc * 8 + tg];
                bb[1] = Ks[nt * 8 + grp][kc * 8 + tg + 4];
                mma_tf32(s[nt], qa[kc], bb);
            }
        }

        // --- mask OOB keys, row max ---
        float rmax0 = NEG_INF, rmax1 = NEG_INF;
#pragma unroll
        for (int nt = 0; nt < 4; nt++) {
            int colg = k0 + nt * 8 + 2 * tg;
            if (colg >= len)     { s[nt][0] = NEG_INF; s[nt][2] = NEG_INF; }
            if (colg + 1 >= len) { s[nt][1] = NEG_INF; s[nt][3] = NEG_INF; }
            rmax0 = fmaxf(rmax0, fmaxf(s[nt][0], s[nt][1]));
            rmax1 = fmaxf(rmax1, fmaxf(s[nt][2], s[nt][3]));
        }
        rmax0 = fmaxf(rmax0, __shfl_xor_sync(0xffffffffu, rmax0, 1));
        rmax0 = fmaxf(rmax0, __shfl_xor_sync(0xffffffffu, rmax0, 2));
        rmax1 = fmaxf(rmax1, __shfl_xor_sync(0xffffffffu, rmax1, 1));
        rmax1 = fmaxf(rmax1, __shfl_xor_sync(0xffffffffu, rmax1, 2));

        float mn0 = fmaxf(m0, rmax0);
        float mn1 = fmaxf(m1, rmax1);
        float a0  = __expf(m0 - mn0);   // exp(-inf)=0 on first tile
        float a1  = __expf(m1 - mn1);
        l0 *= a0; l1 *= a1;
#pragma unroll
        for (int dt = 0; dt < 4; dt++) {
            o[dt][0] *= a0; o[dt][1] *= a0;
            o[dt][2] *= a1; o[dt][3] *= a1;
        }
        m0 = mn0; m1 = mn1;

        // --- exp + row sums ---
        float rs0 = 0.f, rs1 = 0.f;
#pragma unroll
        for (int nt = 0; nt < 4; nt++) {
            s[nt][0] = __expf(s[nt][0] - mn0);
            s[nt][1] = __expf(s[nt][1] - mn0);
            s[nt][2] = __expf(s[nt][2] - mn1);
            s[nt][3] = __expf(s[nt][3] - mn1);
            rs0 += s[nt][0] + s[nt][1];
            rs1 += s[nt][2] + s[nt][3];
        }
        rs0 += __shfl_xor_sync(0xffffffffu, rs0, 1);
        rs0 += __shfl_xor_sync(0xffffffffu, rs0, 2);
        rs1 += __shfl_xor_sync(0xffffffffu, rs1, 1);
        rs1 += __shfl_xor_sync(0xffffffffu, rs1, 2);
        l0 += rs0; l1 += rs1;

        // --- P (C-layout) -> A-layout via quad shfls, then O += P V ---
        const int src1 = (lane & ~3) | (tg >> 1);
        const int src2 = src1 + 2;
        const bool odd = tg & 1;
#pragma unroll
        for (int kc2 = 0; kc2 < 4; kc2++) {
            float u0 = __shfl_sync(0xffffffffu, s[kc2][0], src1);
            float u1 = __shfl_sync(0xffffffffu, s[kc2][1], src1);
            float w0 = __shfl_sync(0xffffffffu, s[kc2][2], src1);
            float w1 = __shfl_sync(0xffffffffu, s[kc2][3], src1);
            float x0 = __shfl_sync(0xffffffffu, s[kc2][0], src2);
            float x1 = __shfl_sync(0xffffffffu, s[kc2][1], src2);
            float y0 = __shfl_sync(0xffffffffu, s[kc2][2], src2);
            float y1 = __shfl_sync(0xffffffffu, s[kc2][3], src2);
            uint32_t pa[4];
            pa[0] = f2tf32(odd ? u1 : u0);
            pa[1] = f2tf32(odd ? w1 : w0);
            pa[2] = f2tf32(odd ? x1 : x0);
            pa[3] = f2tf32(odd ? y1 : y0);
#pragma unroll
            for (int dt = 0; dt < 4; dt++) {
                uint32_t bb[2];
                bb[0] = Vs[kc2 * 8 + tg][dt * 8 + grp];
                bb[1] = Vs[kc2 * 8 + tg + 4][dt * 8 + grp];
                mma_tf32(o[dt], pa, bb);
            }
        }
        __syncthreads();
    }

    // --- epilogue: normalize + store ---
    const float inv0 = 1.0f / l0;
    const float inv1 = 1.0f / l1;
    const int r0 = qw + grp;
    const int r1 = r0 + 8;
#pragma unroll
    for (int dt = 0; dt < 4; dt++) {
        int d = dt * 8 + 2 * tg;
        if (r0 < len) {
            float2 v = make_float2(o[dt][0] * inv0, o[dt][1] * inv0);
            *(float2*)(g_ao + (size_t)(off + r0) * D_ + h * HD_ + d) = v;
        }
        if (r1 < len) {
            float2 v = make_float2(o[dt][2] * inv1, o[dt][3] * inv1);
            *(float2*)(g_ao + (size_t)(off + r1) * D_ + h * HD_ + d) = v;
        }
    }
}

// ---------------------------------------------------------------------------
// Launch: offsets -> LN -> QKV GEMM -> attention -> out-proj(+residual).
// ---------------------------------------------------------------------------
extern "C" void kernel_launch(void* const* d_in, const int* in_sizes, int n_in,
                              void* d_out, int out_size) {
    const float* x     = (const float*)d_in[0];
    const float* in_w  = (const float*)d_in[1];
    const float* in_b  = (const float*)d_in[2];
    const float* out_w = (const float*)d_in[3];
    const float* out_b = (const float*)d_in[4];
    const float* gamma = (const float*)d_in[5];
    const float* beta  = (const float*)d_in[6];
    const int*   offs  = (const int*)d_in[7];

    const int T = in_sizes[0] / D_;          // 12137
    const int B = in_sizes[7] - 1;           // 16 (size 17 if int32, 34/2 if int64)
    const int Bc = (B >= 32) ? (in_sizes[7] / 2 - 1) : B;  // robust either dtype

    void *ph, *pq, *po;
    cudaGetSymbolAddress(&ph, g_h);
    cudaGetSymbolAddress(&pq, g_qkv);
    cudaGetSymbolAddress(&po, g_ao);
    float* h_ptr = (float*)ph;
    float* qkv   = (float*)pq;
    float* ao    = (float*)po;

    conv_offs_kernel<<<1, 32>>>(offs, Bc + 1);

    {   // LayerNorm
        dim3 blk(32, 8);
        ln_kernel<<<(T + 7) / 8, blk>>>(x, gamma, beta, T);
    }
    {   // QKV projection: [T,256] x [768,256]^T
        dim3 grid((3 * D_) / 64, (T + 127) / 128);
        gemm_kernel<false><<<grid, 256>>>(h_ptr, in_w, in_b, nullptr, qkv,
                                          T, 3 * D_, D_);
    }
    {   // tf32 mma flash attention: 64 queries per block
        dim3 grid(16 /* ceil(1024/64) */, H_, Bc);
        attn_mma_kernel<<<grid, 128>>>();
    }
    {   // Output projection + residual
        dim3 grid(D_ / 64, (T + 127) / 128);
        gemm_kernel<true><<<grid, 256>>>(ao, out_w, out_b, x, (float*)d_out,
                                         T, D_, D_);
    }
}

// round 4
// speedup vs baseline: 3.1419x; 2.1327x over previous
#include <cuda_runtime.h>
#include <math.h>
#include <stdint.h>

#define D_    256
#define H_    8
#define HD_   32
#define MAXT_ 16384

// Scratch (static device globals — allocation-free, within harness rules)
__device__ float g_h[(size_t)MAXT_ * D_];        // LayerNorm output      [T,256]
__device__ float g_qkv[(size_t)MAXT_ * 3 * D_];  // fused qkv projection  [T,768]
__device__ float g_ao[(size_t)MAXT_ * D_];       // attention output      [T,256]
__device__ int   g_offs[64];                     // canonical int32 batch offsets

// ---------------------------------------------------------------------------
// helpers
// ---------------------------------------------------------------------------
__device__ __forceinline__ uint32_t f2tf32(float x) {
    uint32_t r;
    asm("cvt.rna.tf32.f32 %0, %1;" : "=r"(r) : "f"(x));
    return r;
}
__device__ __forceinline__ float ex2f(float x) {
    float r;
    asm("ex2.approx.f32 %0, %1;" : "=f"(r) : "f"(x));
    return r;
}
__device__ __forceinline__ void mma_tf32(float c[4], const uint32_t a[4],
                                         const uint32_t b[2]) {
    asm volatile(
        "mma.sync.aligned.m16n8k8.row.col.f32.tf32.tf32.f32 "
        "{%0,%1,%2,%3}, {%4,%5,%6,%7}, {%8,%9}, {%0,%1,%2,%3};\n"
        : "+f"(c[0]), "+f"(c[1]), "+f"(c[2]), "+f"(c[3])
        : "r"(a[0]), "r"(a[1]), "r"(a[2]), "r"(a[3]), "r"(b[0]), "r"(b[1]));
}

// ---------------------------------------------------------------------------
// Kernel 0: canonicalize batch_offsets (int32 or int64 — auto-detect).
// ---------------------------------------------------------------------------
__global__ void conv_offs_kernel(const int* __restrict__ raw, int n) {
    if (threadIdx.x == 0) {
        bool is64 = (raw[1] == 0);
        for (int i = 0; i < n; i++)
            g_offs[i] = is64 ? raw[2 * i] : raw[i];
    }
}

// ---------------------------------------------------------------------------
// Kernel 1: LayerNorm. One warp per token.
// ---------------------------------------------------------------------------
__global__ void ln_kernel(const float* __restrict__ x,
                          const float* __restrict__ gamma,
                          const float* __restrict__ beta, int T) {
    int t = blockIdx.x * blockDim.y + threadIdx.y;
    if (t >= T) return;
    int lane = threadIdx.x;
    const float* row = x + (size_t)t * D_;
    float v[8];
    float sum = 0.f, sq = 0.f;
#pragma unroll
    for (int i = 0; i < 8; i++) {
        v[i] = row[lane + i * 32];
        sum += v[i];
        sq  += v[i] * v[i];
    }
#pragma unroll
    for (int o = 16; o > 0; o >>= 1) {
        sum += __shfl_xor_sync(0xffffffffu, sum, o);
        sq  += __shfl_xor_sync(0xffffffffu, sq, o);
    }
    float mu  = sum * (1.0f / D_);
    float var = sq * (1.0f / D_) - mu * mu;
    float rs  = rsqrtf(var + 1e-5f);
    float* out = g_h + (size_t)t * D_;
#pragma unroll
    for (int i = 0; i < 8; i++) {
        int c = lane + i * 32;
        out[c] = (v[i] - mu) * rs * gamma[c] + beta[c];
    }
}

// ---------------------------------------------------------------------------
// Kernel 2/4: tf32 tensor-core GEMM  C[M,N] = A[M,K=256] @ W[N,K]^T + bias
// (+ residual). Block 64x64, BK=32, 4 warps (2x2), 32x32 per warp
// (2 m-frags x 4 n-frags of m16n8k8). Smem in fragment-order layout
// [row][tg][j] (row stride 36) so fragment loads are LDS.128.
// Register-prefetch double buffering on the global loads.
// ---------------------------------------------------------------------------
template<bool RES>
__global__ __launch_bounds__(128)
void gemm_tf32_kernel(const float* __restrict__ A, const float* __restrict__ W,
                      const float* __restrict__ bias, const float* __restrict__ res,
                      float* __restrict__ C, int M, int N) {
    __shared__ uint32_t AS[64 * 36];
    __shared__ uint32_t WS[64 * 36];
    const int tid  = threadIdx.x;
    const int warp = tid >> 5, lane = tid & 31;
    const int tg = lane & 3, grp = lane >> 2;
    const int wm = warp >> 1, wn = warp & 1;
    const int m0 = blockIdx.y * 64, n0 = blockIdx.x * 64;

    const int lrow = tid >> 3;          // loader row (p-chunks add 16)
    const int lc0  = (tid & 7) * 4;     // loader col (const across p)
    const int lj   = lc0 >> 2;

    float4 af[4], wf[4];
#pragma unroll
    for (int p = 0; p < 4; p++) {
        int r = lrow + p * 16;
        int gr = m0 + r;
        af[p] = (gr < M) ? *(const float4*)(A + (size_t)gr * 256 + lc0)
                         : make_float4(0.f, 0.f, 0.f, 0.f);
        wf[p] = *(const float4*)(W + (size_t)(n0 + r) * 256 + lc0);
    }

    float acc[2][4][4];
#pragma unroll
    for (int mt = 0; mt < 2; mt++)
#pragma unroll
        for (int nt = 0; nt < 4; nt++)
#pragma unroll
            for (int i = 0; i < 4; i++) acc[mt][nt][i] = 0.f;

    for (int k0 = 0; k0 < 256; k0 += 32) {
        // store prefetched tile (fragment-order, tf32)
#pragma unroll
        for (int p = 0; p < 4; p++) {
            int r = lrow + p * 16;
            const float* ap = (const float*)&af[p];
            const float* wp = (const float*)&wf[p];
#pragma unroll
            for (int e = 0; e < 4; e++) {
                AS[r * 36 + e * 8 + lj] = f2tf32(ap[e]);
                WS[r * 36 + e * 8 + lj] = f2tf32(wp[e]);
            }
        }
        __syncthreads();

        if (k0 + 32 < 256) {
            int k1 = k0 + 32;
#pragma unroll
            for (int p = 0; p < 4; p++) {
                int r = lrow + p * 16;
                int gr = m0 + r;
                af[p] = (gr < M) ? *(const float4*)(A + (size_t)gr * 256 + k1 + lc0)
                                 : make_float4(0.f, 0.f, 0.f, 0.f);
                wf[p] = *(const float4*)(W + (size_t)(n0 + r) * 256 + k1 + lc0);
            }
        }

        uint32_t bR[4][8];
#pragma unroll
        for (int nt = 0; nt < 4; nt++) {
            int r = wn * 32 + nt * 8 + grp;
            *(float4*)&bR[nt][0] = *(const float4*)&WS[r * 36 + tg * 8];
            *(float4*)&bR[nt][4] = *(const float4*)&WS[r * 36 + tg * 8 + 4];
        }
#pragma unroll
        for (int mt = 0; mt < 2; mt++) {
            int r = wm * 32 + mt * 16 + grp;
            uint32_t aLo[8], aHi[8];
            *(float4*)&aLo[0] = *(const float4*)&AS[r * 36 + tg * 8];
            *(float4*)&aLo[4] = *(const float4*)&AS[r * 36 + tg * 8 + 4];
            *(float4*)&aHi[0] = *(const float4*)&AS[(r + 8) * 36 + tg * 8];
            *(float4*)&aHi[4] = *(const float4*)&AS[(r + 8) * 36 + tg * 8 + 4];
#pragma unroll
            for (int kc = 0; kc < 4; kc++) {
                uint32_t aa[4] = {aLo[2 * kc], aHi[2 * kc],
                                  aLo[2 * kc + 1], aHi[2 * kc + 1]};
#pragma unroll
                for (int nt = 0; nt < 4; nt++) {
                    uint32_t bb[2] = {bR[nt][2 * kc], bR[nt][2 * kc + 1]};
                    mma_tf32(acc[mt][nt], aa, bb);
                }
            }
        }
        __syncthreads();
    }

    // epilogue: bias (+residual), float2 stores
#pragma unroll
    for (int mt = 0; mt < 2; mt++) {
        int r0 = m0 + wm * 32 + mt * 16 + grp;
        int r1 = r0 + 8;
#pragma unroll
        for (int nt = 0; nt < 4; nt++) {
            int col = n0 + wn * 32 + nt * 8 + 2 * tg;
            float2 bv = *(const float2*)(bias + col);
            if (r0 < M) {
                float2 out = make_float2(acc[mt][nt][0] + bv.x,
                                         acc[mt][nt][1] + bv.y);
                if (RES) {
                    float2 rr = *(const float2*)(res + (size_t)r0 * N + col);
                    out.x += rr.x; out.y += rr.y;
                }
                *(float2*)(C + (size_t)r0 * N + col) = out;
            }
            if (r1 < M) {
                float2 out = make_float2(acc[mt][nt][2] + bv.x,
                                         acc[mt][nt][3] + bv.y);
                if (RES) {
                    float2 rr = *(const float2*)(res + (size_t)r1 * N + col);
                    out.x += rr.x; out.y += rr.y;
                }
                *(float2*)(C + (size_t)r1 * N + col) = out;
            }
        }
    }
}

// ---------------------------------------------------------------------------
// Kernel 3: tf32 mma.sync flash attention, v2.
// Block = 4 warps x 32 queries = 128 queries per (batch, head).
// K-tile = 32 keys. KB stores K with the n-axis key permutation
// sigma(n) = (n>>1) + (n&1)*4, which makes the S C-fragment register layout
// IDENTICAL to the P A-fragment layout needed by P·V (zero shuffles).
// KB/VB are in fragment order (per-lane contiguous 8-word groups, stride 36)
// so all fragment loads are LDS.128. Softmax in base-2 (ex2.approx).
// ---------------------------------------------------------------------------
__global__ __launch_bounds__(128)
void attn_mma_kernel() {
    const int b = blockIdx.z, h = blockIdx.y;
    const int off = g_offs[b];
    const int len = g_offs[b + 1] - off;
    const int q0  = blockIdx.x * 128;
    if (q0 >= len) return;

    const int tid  = threadIdx.x;
    const int warp = tid >> 5, lane = tid & 31;
    const int tg = lane & 3, grp = lane >> 2;
    const int qw = q0 + warp * 32;

    const float scale2 = 0.17677669529663687f * 1.4426950408889634f; // /sqrt(32)*log2e
    const float NEG_INF = -INFINITY;

    __shared__ uint32_t KB[32 * 36];
    __shared__ uint32_t VB[32 * 36];

    const float* qbase = g_qkv + (size_t)off * 768 + h * HD_;
    const float* kbase = qbase + D_;
    const float* vbase = qbase + 2 * D_;

    // --- Q fragments: 2 m-tiles x 4 k-chunks ---
    uint32_t qa[2][4][4];
#pragma unroll
    for (int mt = 0; mt < 2; mt++) {
        int r0 = qw + mt * 16 + grp, r1 = r0 + 8;
#pragma unroll
        for (int kc = 0; kc < 4; kc++) {
            int d0 = kc * 8 + tg, d1 = d0 + 4;
            qa[mt][kc][0] = f2tf32(r0 < len ? qbase[(size_t)r0 * 768 + d0] * scale2 : 0.f);
            qa[mt][kc][1] = f2tf32(r1 < len ? qbase[(size_t)r1 * 768 + d0] * scale2 : 0.f);
            qa[mt][kc][2] = f2tf32(r0 < len ? qbase[(size_t)r0 * 768 + d1] * scale2 : 0.f);
            qa[mt][kc][3] = f2tf32(r1 < len ? qbase[(size_t)r1 * 768 + d1] * scale2 : 0.f);
        }
    }

    float o[2][4][4];
#pragma unroll
    for (int mt = 0; mt < 2; mt++)
#pragma unroll
        for (int dt = 0; dt < 4; dt++)
#pragma unroll
            for (int i = 0; i < 4; i++) o[mt][dt][i] = 0.f;
    float mrow[2][2] = {{NEG_INF, NEG_INF}, {NEG_INF, NEG_INF}};
    float lrow[2][2] = {{0.f, 0.f}, {0.f, 0.f}};

    // loader geometry: 256 float4 slots = 32 keys x 8 d4-slots
    const int keyA = tid >> 3;            // p=0: keys 0..15
    const int keyB = (tid + 128) >> 3;    // p=1: keys 16..31
    const int d4   = (tid & 7) * 4;

    float4 kf[2], vf[2];
    {   // prefetch tile 0 (len >= 512 so always fully valid, but guard anyway)
        int keys[2] = {keyA, keyB};
#pragma unroll
        for (int p = 0; p < 2; p++) {
            bool v = keys[p] < len;
            kf[p] = v ? *(const float4*)(kbase + (size_t)keys[p] * 768 + d4)
                      : make_float4(0.f, 0.f, 0.f, 0.f);
            vf[p] = v ? *(const float4*)(vbase + (size_t)keys[p] * 768 + d4)
                      : make_float4(0.f, 0.f, 0.f, 0.f);
        }
    }

    for (int k0 = 0; k0 < len; k0 += 32) {
        // --- store prefetched K/V tile into fragment-order smem ---
        {
            int keys[2] = {keyA, keyB};
            const int kc = d4 >> 3;          // K: k-chunk
            const int bq = (d4 >> 2) & 1;    // K: b-index
            const int dt = d4 >> 3;          // V: d-tile
#pragma unroll
            for (int p = 0; p < 2; p++) {
                int key = keys[p];
                int nt = key >> 3, j = key & 7;
                int npos = (j & 3) * 2 + (j >> 2);     // sigma^-1(j)
                int kc2 = key >> 3;
                int tgv = key & 3, bv = (key >> 2) & 1;
                const float* kp = (const float*)&kf[p];
                const float* vp = (const float*)&vf[p];
#pragma unroll
                for (int e = 0; e < 4; e++) {
                    KB[(npos * 4 + e) * 36 + kc * 8 + nt * 2 + bq] = f2tf32(kp[e]);
                    int gp = (d4 & 7) + e;
                    VB[(gp * 4 + tgv) * 36 + kc2 * 8 + dt * 2 + bv] = f2tf32(vp[e]);
                }
            }
        }
        __syncthreads();

        // --- prefetch next tile (overlaps with compute) ---
        {
            int k1 = k0 + 32;
            if (k1 < len) {
                int keys[2] = {k1 + keyA, k1 + keyB};
#pragma unroll
                for (int p = 0; p < 2; p++) {
                    bool v = keys[p] < len;
                    kf[p] = v ? *(const float4*)(kbase + (size_t)keys[p] * 768 + d4)
                              : make_float4(0.f, 0.f, 0.f, 0.f);
                    vf[p] = v ? *(const float4*)(vbase + (size_t)keys[p] * 768 + d4)
                              : make_float4(0.f, 0.f, 0.f, 0.f);
                }
            }
        }

        // --- S = Q K^T (keys sigma-permuted within each 8-group) ---
        float s[2][4][4];
#pragma unroll
        for (int mt = 0; mt < 2; mt++)
#pragma unroll
            for (int nt = 0; nt < 4; nt++)
#pragma unroll
                for (int i = 0; i < 4; i++) s[mt][nt][i] = 0.f;
#pragma unroll
        for (int kc = 0; kc < 4; kc++) {
            uint32_t kb8[8];
            *(float4*)&kb8[0] = *(const float4*)&KB[lane * 36 + kc * 8];
            *(float4*)&kb8[4] = *(const float4*)&KB[lane * 36 + kc * 8 + 4];
#pragma unroll
            for (int mt = 0; mt < 2; mt++)
#pragma unroll
                for (int nt = 0; nt < 4; nt++) {
                    uint32_t bb[2] = {kb8[nt * 2], kb8[nt * 2 + 1]};
                    mma_tf32(s[mt][nt], qa[mt][kc], bb);
                }
        }

        // --- mask tail keys (regs 0,2 <-> key nt*8+tg; regs 1,3 <-> +4) ---
        if (k0 + 32 > len) {
#pragma unroll
            for (int nt = 0; nt < 4; nt++) {
                bool m0bad = (k0 + nt * 8 + tg) >= len;
                bool m1bad = (k0 + nt * 8 + tg + 4) >= len;
#pragma unroll
                for (int mt = 0; mt < 2; mt++) {
                    if (m0bad) { s[mt][nt][0] = NEG_INF; s[mt][nt][2] = NEG_INF; }
                    if (m1bad) { s[mt][nt][1] = NEG_INF; s[mt][nt][3] = NEG_INF; }
                }
            }
        }

        // --- online softmax (base-2) ---
#pragma unroll
        for (int mt = 0; mt < 2; mt++) {
            float rlo = NEG_INF, rhi = NEG_INF;
#pragma unroll
            for (int nt = 0; nt < 4; nt++) {
                rlo = fmaxf(rlo, fmaxf(s[mt][nt][0], s[mt][nt][1]));
                rhi = fmaxf(rhi, fmaxf(s[mt][nt][2], s[mt][nt][3]));
            }
            rlo = fmaxf(rlo, __shfl_xor_sync(0xffffffffu, rlo, 1));
            rlo = fmaxf(rlo, __shfl_xor_sync(0xffffffffu, rlo, 2));
            rhi = fmaxf(rhi, __shfl_xor_sync(0xffffffffu, rhi, 1));
            rhi = fmaxf(rhi, __shfl_xor_sync(0xffffffffu, rhi, 2));

            float mlo = fmaxf(mrow[mt][0], rlo);
            float mhi = fmaxf(mrow[mt][1], rhi);
            float alo = ex2f(mrow[mt][0] - mlo);
            float ahi = ex2f(mrow[mt][1] - mhi);
            lrow[mt][0] *= alo; lrow[mt][1] *= ahi;
#pragma unroll
            for (int dt = 0; dt < 4; dt++) {
                o[mt][dt][0] *= alo; o[mt][dt][1] *= alo;
                o[mt][dt][2] *= ahi; o[mt][dt][3] *= ahi;
            }
            mrow[mt][0] = mlo; mrow[mt][1] = mhi;

            float slo = 0.f, shi = 0.f;
#pragma unroll
            for (int nt = 0; nt < 4; nt++) {
                s[mt][nt][0] = ex2f(s[mt][nt][0] - mlo);
                s[mt][nt][1] = ex2f(s[mt][nt][1] - mlo);
                s[mt][nt][2] = ex2f(s[mt][nt][2] - mhi);
                s[mt][nt][3] = ex2f(s[mt][nt][3] - mhi);
                slo += s[mt][nt][0] + s[mt][nt][1];
                shi += s[mt][nt][2] + s[mt][nt][3];
            }
            slo += __shfl_xor_sync(0xffffffffu, slo, 1);
            slo += __shfl_xor_sync(0xffffffffu, slo, 2);
            shi += __shfl_xor_sync(0xffffffffu, shi, 1);
            shi += __shfl_xor_sync(0xffffffffu, shi, 2);
            lrow[mt][0] += slo; lrow[mt][1] += shi;
        }

        // --- O += P V (P already in A-layout thanks to sigma; no shuffles) ---
#pragma unroll
        for (int kc2 = 0; kc2 < 4; kc2++) {
            uint32_t vb8[8];
            *(float4*)&vb8[0] = *(const float4*)&VB[lane * 36 + kc2 * 8];
            *(float4*)&vb8[4] = *(const float4*)&VB[lane * 36 + kc2 * 8 + 4];
#pragma unroll
            for (int mt = 0; mt < 2; mt++) {
                uint32_t pa[4] = {f2tf32(s[mt][kc2][0]), f2tf32(s[mt][kc2][2]),
                                  f2tf32(s[mt][kc2][1]), f2tf32(s[mt][kc2][3])};
#pragma unroll
                for (int dt = 0; dt < 4; dt++) {
                    uint32_t bb[2] = {vb8[dt * 2], vb8[dt * 2 + 1]};
                    mma_tf32(o[mt][dt], pa, bb);
                }
            }
        }
        __syncthreads();
    }

    // --- epilogue: normalize + store ---
#pragma unroll
    for (int mt = 0; mt < 2; mt++) {
        float ilo = 1.0f / lrow[mt][0];
        float ihi = 1.0f / lrow[mt][1];
        int r0 = qw + mt * 16 + grp, r1 = r0 + 8;
#pragma unroll
        for (int dt = 0; dt < 4; dt++) {
            int d = dt * 8 + 2 * tg;
            if (r0 < len) {
                float2 v = make_float2(o[mt][dt][0] * ilo, o[mt][dt][1] * ilo);
                *(float2*)(g_ao + (size_t)(off + r0) * D_ + h * HD_ + d) = v;
            }
            if (r1 < len) {
                float2 v = make_float2(o[mt][dt][2] * ihi, o[mt][dt][3] * ihi);
                *(float2*)(g_ao + (size_t)(off + r1) * D_ + h * HD_ + d) = v;
            }
        }
    }
}

// ---------------------------------------------------------------------------
// Launch: offsets -> LN -> QKV GEMM -> attention -> out-proj(+residual).
// ---------------------------------------------------------------------------
extern "C" void kernel_launch(void* const* d_in, const int* in_sizes, int n_in,
                              void* d_out, int out_size) {
    const float* x     = (const float*)d_in[0];
    const float* in_w  = (const float*)d_in[1];
    const float* in_b  = (const float*)d_in[2];
    const float* out_w = (const float*)d_in[3];
    const float* out_b = (const float*)d_in[4];
    const float* gamma = (const float*)d_in[5];
    const float* beta  = (const float*)d_in[6];
    const int*   offs  = (const int*)d_in[7];

    const int T = in_sizes[0] / D_;
    const int B = in_sizes[7] - 1;
    const int Bc = (B >= 32) ? (in_sizes[7] / 2 - 1) : B;   // robust either dtype

    void *ph, *pq, *po;
    cudaGetSymbolAddress(&ph, g_h);
    cudaGetSymbolAddress(&pq, g_qkv);
    cudaGetSymbolAddress(&po, g_ao);
    float* h_ptr = (float*)ph;
    float* qkv   = (float*)pq;
    float* ao    = (float*)po;

    conv_offs_kernel<<<1, 32>>>(offs, Bc + 1);

    {   // LayerNorm
        dim3 blk(32, 8);
        ln_kernel<<<(T + 7) / 8, blk>>>(x, gamma, beta, T);
    }
    {   // QKV projection: [T,256] x [768,256]^T  (tf32 tensor)
        dim3 grid((3 * D_) / 64, (T + 63) / 64);
        gemm_tf32_kernel<false><<<grid, 128>>>(h_ptr, in_w, in_b, nullptr,
                                               qkv, T, 3 * D_);
    }
    {   // tf32 mma flash attention: 128 queries per block
        dim3 grid(8 /* ceil(1024/128) */, H_, Bc);
        attn_mma_kernel<<<grid, 128>>>();
    }
    {   // Output projection + residual  (tf32 tensor)
        dim3 grid(D_ / 64, (T + 63) / 64);
        gemm_tf32_kernel<true><<<grid, 128>>>(ao, out_w, out_b, x,
                                              (float*)d_out, T, D_);
    }
}

// round 5
// speedup vs baseline: 3.2998x; 1.0502x over previous
#include <cuda_runtime.h>
#include <math.h>
#include <stdint.h>

#define D_    256
#define H_    8
#define HD_   32
#define MAXT_ 16384

// Scratch (static device globals — allocation-free, within harness rules)
__device__ float g_h[(size_t)MAXT_ * D_];        // LayerNorm output      [T,256]
__device__ float g_qkv[(size_t)MAXT_ * 3 * D_];  // fused qkv projection  [T,768]
__device__ float g_ao[(size_t)MAXT_ * D_];       // attention output      [T,256]
__device__ int   g_offs[64];                     // canonical int32 batch offsets

// ---------------------------------------------------------------------------
// helpers. tf32 HMMA reads only the tf32 bit-field of each operand register,
// so feeding raw fp32 bits == round-toward-zero tf32 (CUTLASS "fastest" mode).
// No cvt instructions needed anywhere on the hot path.
// ---------------------------------------------------------------------------
__device__ __forceinline__ uint32_t f2b(float x) { return __float_as_uint(x); }
__device__ __forceinline__ float ex2f(float x) {
    float r;
    asm("ex2.approx.f32 %0, %1;" : "=f"(r) : "f"(x));
    return r;
}
__device__ __forceinline__ void mma_tf32(float c[4], const uint32_t a[4],
                                         const uint32_t b[2]) {
    asm volatile(
        "mma.sync.aligned.m16n8k8.row.col.f32.tf32.tf32.f32 "
        "{%0,%1,%2,%3}, {%4,%5,%6,%7}, {%8,%9}, {%0,%1,%2,%3};\n"
        : "+f"(c[0]), "+f"(c[1]), "+f"(c[2]), "+f"(c[3])
        : "r"(a[0]), "r"(a[1]), "r"(a[2]), "r"(a[3]), "r"(b[0]), "r"(b[1]));
}

// ---------------------------------------------------------------------------
// Kernel 1: LayerNorm (one warp per token) + offsets canonicalization
// (block 0, thread 0 — attention launches later in-stream).
// ---------------------------------------------------------------------------
__global__ void ln_kernel(const float* __restrict__ x,
                          const float* __restrict__ gamma,
                          const float* __restrict__ beta, int T,
                          const int* __restrict__ raw_offs, int nOffs) {
    if (blockIdx.x == 0 && threadIdx.x == 0 && threadIdx.y == 0) {
        bool is64 = (raw_offs[1] == 0);   // int64 layout: high word of offs[0]
        for (int i = 0; i < nOffs; i++)
            g_offs[i] = is64 ? raw_offs[2 * i] : raw_offs[i];
    }
    int t = blockIdx.x * blockDim.y + threadIdx.y;
    if (t >= T) return;
    int lane = threadIdx.x;
    const float* row = x + (size_t)t * D_;
    float v[8];
    float sum = 0.f, sq = 0.f;
#pragma unroll
    for (int i = 0; i < 8; i++) {
        v[i] = row[lane + i * 32];
        sum += v[i];
        sq  += v[i] * v[i];
    }
#pragma unroll
    for (int o = 16; o > 0; o >>= 1) {
        sum += __shfl_xor_sync(0xffffffffu, sum, o);
        sq  += __shfl_xor_sync(0xffffffffu, sq, o);
    }
    float mu  = sum * (1.0f / D_);
    float var = sq * (1.0f / D_) - mu * mu;
    float rs  = rsqrtf(var + 1e-5f);
    float* out = g_h + (size_t)t * D_;
#pragma unroll
    for (int i = 0; i < 8; i++) {
        int c = lane + i * 32;
        out[c] = (v[i] - mu) * rs * gamma[c] + beta[c];
    }
}

// ---------------------------------------------------------------------------
// Kernel 2/4: tf32 tensor-core GEMM  C[M,N] = A[M,K=256] @ W[N,K]^T + bias
// (+ residual). Block 64x64, BK=32, 4 warps (2x2), 32x32 per warp.
// Fragment-order smem (stride 36) -> LDS.128 fragment loads.
// Register-prefetch double buffering.
// ---------------------------------------------------------------------------
template<bool RES>
__global__ __launch_bounds__(128)
void gemm_tf32_kernel(const float* __restrict__ A, const float* __restrict__ W,
                      const float* __restrict__ bias, const float* __restrict__ res,
                      float* __restrict__ C, int M, int N) {
    __shared__ uint32_t AS[64 * 36];
    __shared__ uint32_t WS[64 * 36];
    const int tid  = threadIdx.x;
    const int warp = tid >> 5, lane = tid & 31;
    const int tg = lane & 3, grp = lane >> 2;
    const int wm = warp >> 1, wn = warp & 1;
    const int m0 = blockIdx.y * 64, n0 = blockIdx.x * 64;

    const int lrow = tid >> 3;
    const int lc0  = (tid & 7) * 4;
    const int lj   = lc0 >> 2;

    float4 af[4], wf[4];
#pragma unroll
    for (int p = 0; p < 4; p++) {
        int r = lrow + p * 16;
        int gr = m0 + r;
        af[p] = (gr < M) ? *(const float4*)(A + (size_t)gr * 256 + lc0)
                         : make_float4(0.f, 0.f, 0.f, 0.f);
        wf[p] = *(const float4*)(W + (size_t)(n0 + r) * 256 + lc0);
    }

    float acc[2][4][4];
#pragma unroll
    for (int mt = 0; mt < 2; mt++)
#pragma unroll
        for (int nt = 0; nt < 4; nt++)
#pragma unroll
            for (int i = 0; i < 4; i++) acc[mt][nt][i] = 0.f;

    for (int k0 = 0; k0 < 256; k0 += 32) {
#pragma unroll
        for (int p = 0; p < 4; p++) {
            int r = lrow + p * 16;
            const float* ap = (const float*)&af[p];
            const float* wp = (const float*)&wf[p];
#pragma unroll
            for (int e = 0; e < 4; e++) {
                AS[r * 36 + e * 8 + lj] = f2b(ap[e]);
                WS[r * 36 + e * 8 + lj] = f2b(wp[e]);
            }
        }
        __syncthreads();

        if (k0 + 32 < 256) {
            int k1 = k0 + 32;
#pragma unroll
            for (int p = 0; p < 4; p++) {
                int r = lrow + p * 16;
                int gr = m0 + r;
                af[p] = (gr < M) ? *(const float4*)(A + (size_t)gr * 256 + k1 + lc0)
                                 : make_float4(0.f, 0.f, 0.f, 0.f);
                wf[p] = *(const float4*)(W + (size_t)(n0 + r) * 256 + k1 + lc0);
            }
        }

        uint32_t bR[4][8];
#pragma unroll
        for (int nt = 0; nt < 4; nt++) {
            int r = wn * 32 + nt * 8 + grp;
            *(float4*)&bR[nt][0] = *(const float4*)&WS[r * 36 + tg * 8];
            *(float4*)&bR[nt][4] = *(const float4*)&WS[r * 36 + tg * 8 + 4];
        }
#pragma unroll
        for (int mt = 0; mt < 2; mt++) {
            int r = wm * 32 + mt * 16 + grp;
            uint32_t aLo[8], aHi[8];
            *(float4*)&aLo[0] = *(const float4*)&AS[r * 36 + tg * 8];
            *(float4*)&aLo[4] = *(const float4*)&AS[r * 36 + tg * 8 + 4];
            *(float4*)&aHi[0] = *(const float4*)&AS[(r + 8) * 36 + tg * 8];
            *(float4*)&aHi[4] = *(const float4*)&AS[(r + 8) * 36 + tg * 8 + 4];
#pragma unroll
            for (int kc = 0; kc < 4; kc++) {
                uint32_t aa[4] = {aLo[2 * kc], aHi[2 * kc],
                                  aLo[2 * kc + 1], aHi[2 * kc + 1]};
#pragma unroll
                for (int nt = 0; nt < 4; nt++) {
                    uint32_t bb[2] = {bR[nt][2 * kc], bR[nt][2 * kc + 1]};
                    mma_tf32(acc[mt][nt], aa, bb);
                }
            }
        }
        __syncthreads();
    }

#pragma unroll
    for (int mt = 0; mt < 2; mt++) {
        int r0 = m0 + wm * 32 + mt * 16 + grp;
        int r1 = r0 + 8;
#pragma unroll
        for (int nt = 0; nt < 4; nt++) {
            int col = n0 + wn * 32 + nt * 8 + 2 * tg;
            float2 bv = *(const float2*)(bias + col);
            if (r0 < M) {
                float2 out = make_float2(acc[mt][nt][0] + bv.x,
                                         acc[mt][nt][1] + bv.y);
                if (RES) {
                    float2 rr = *(const float2*)(res + (size_t)r0 * N + col);
                    out.x += rr.x; out.y += rr.y;
                }
                *(float2*)(C + (size_t)r0 * N + col) = out;
            }
            if (r1 < M) {
                float2 out = make_float2(acc[mt][nt][2] + bv.x,
                                         acc[mt][nt][3] + bv.y);
                if (RES) {
                    float2 rr = *(const float2*)(res + (size_t)r1 * N + col);
                    out.x += rr.x; out.y += rr.y;
                }
                *(float2*)(C + (size_t)r1 * N + col) = out;
            }
        }
    }
}

// ---------------------------------------------------------------------------
// Kernel 3: tf32 mma.sync flash attention, v3.
// Block = 4 warps x 32 queries = 128 queries per (batch, head).
// sigma(n) = (n>>1)+(n&1)*4 key permutation makes S C-layout == P A-layout
// (zero shuffles). Fragment-order smem -> LDS.128. No tf32 cvts (raw fp32
// bits). Ballot-gated O-rescale: skip alpha multiplies when no row max
// changed (~85% of tiles). Base-2 softmax.
// ---------------------------------------------------------------------------
__global__ __launch_bounds__(128)
void attn_mma_kernel() {
    const int b = blockIdx.z, h = blockIdx.y;
    const int off = g_offs[b];
    const int len = g_offs[b + 1] - off;
    const int q0  = blockIdx.x * 128;
    if (q0 >= len) return;

    const int tid  = threadIdx.x;
    const int warp = tid >> 5, lane = tid & 31;
    const int tg = lane & 3, grp = lane >> 2;
    const int qw = q0 + warp * 32;

    const float scale2 = 0.17677669529663687f * 1.4426950408889634f; // /sqrt(32)*log2e
    const float NEG_INF = -INFINITY;

    __shared__ uint32_t KB[32 * 36];
    __shared__ uint32_t VB[32 * 36];

    const float* qbase = g_qkv + (size_t)off * 768 + h * HD_;
    const float* kbase = qbase + D_;
    const float* vbase = qbase + 2 * D_;

    // --- Q fragments: 2 m-tiles x 4 k-chunks ---
    uint32_t qa[2][4][4];
#pragma unroll
    for (int mt = 0; mt < 2; mt++) {
        int r0 = qw + mt * 16 + grp, r1 = r0 + 8;
#pragma unroll
        for (int kc = 0; kc < 4; kc++) {
            int d0 = kc * 8 + tg, d1 = d0 + 4;
            qa[mt][kc][0] = f2b(r0 < len ? qbase[(size_t)r0 * 768 + d0] * scale2 : 0.f);
            qa[mt][kc][1] = f2b(r1 < len ? qbase[(size_t)r1 * 768 + d0] * scale2 : 0.f);
            qa[mt][kc][2] = f2b(r0 < len ? qbase[(size_t)r0 * 768 + d1] * scale2 : 0.f);
            qa[mt][kc][3] = f2b(r1 < len ? qbase[(size_t)r1 * 768 + d1] * scale2 : 0.f);
        }
    }

    float o[2][4][4];
#pragma unroll
    for (int mt = 0; mt < 2; mt++)
#pragma unroll
        for (int dt = 0; dt < 4; dt++)
#pragma unroll
            for (int i = 0; i < 4; i++) o[mt][dt][i] = 0.f;
    float mrow[2][2] = {{NEG_INF, NEG_INF}, {NEG_INF, NEG_INF}};
    float lrow[2][2] = {{0.f, 0.f}, {0.f, 0.f}};

    // loader geometry: 256 float4 slots = 32 keys x 8 d4-slots
    const int keyA = tid >> 3;
    const int keyB = (tid + 128) >> 3;
    const int d4   = (tid & 7) * 4;

    float4 kf[2], vf[2];
    {
        int keys[2] = {keyA, keyB};
#pragma unroll
        for (int p = 0; p < 2; p++) {
            bool v = keys[p] < len;
            kf[p] = v ? *(const float4*)(kbase + (size_t)keys[p] * 768 + d4)
                      : make_float4(0.f, 0.f, 0.f, 0.f);
            vf[p] = v ? *(const float4*)(vbase + (size_t)keys[p] * 768 + d4)
                      : make_float4(0.f, 0.f, 0.f, 0.f);
        }
    }

    for (int k0 = 0; k0 < len; k0 += 32) {
        // --- store prefetched K/V tile into fragment-order smem ---
        {
            int keys[2] = {keyA, keyB};
            const int kc = d4 >> 3;
            const int bq = (d4 >> 2) & 1;
            const int dt = d4 >> 3;
#pragma unroll
            for (int p = 0; p < 2; p++) {
                int key = keys[p];
                int nt = key >> 3, j = key & 7;
                int npos = (j & 3) * 2 + (j >> 2);     // sigma^-1
                int kc2 = key >> 3;
                int tgv = key & 3, bv = (key >> 2) & 1;
                const float* kp = (const float*)&kf[p];
                const float* vp = (const float*)&vf[p];
#pragma unroll
                for (int e = 0; e < 4; e++) {
                    KB[(npos * 4 + e) * 36 + kc * 8 + nt * 2 + bq] = f2b(kp[e]);
                    int gp = (d4 & 7) + e;
                    VB[(gp * 4 + tgv) * 36 + kc2 * 8 + dt * 2 + bv] = f2b(vp[e]);
                }
            }
        }
        __syncthreads();

        // --- prefetch next tile ---
        {
            int k1 = k0 + 32;
            if (k1 < len) {
                int keys[2] = {k1 + keyA, k1 + keyB};
#pragma unroll
                for (int p = 0; p < 2; p++) {
                    bool v = keys[p] < len;
                    kf[p] = v ? *(const float4*)(kbase + (size_t)keys[p] * 768 + d4)
                              : make_float4(0.f, 0.f, 0.f, 0.f);
                    vf[p] = v ? *(const float4*)(vbase + (size_t)keys[p] * 768 + d4)
                              : make_float4(0.f, 0.f, 0.f, 0.f);
                }
            }
        }

        // --- S = Q K^T ---
        float s[2][4][4];
#pragma unroll
        for (int mt = 0; mt < 2; mt++)
#pragma unroll
            for (int nt = 0; nt < 4; nt++)
#pragma unroll
                for (int i = 0; i < 4; i++) s[mt][nt][i] = 0.f;
#pragma unroll
        for (int kc = 0; kc < 4; kc++) {
            uint32_t kb8[8];
            *(float4*)&kb8[0] = *(const float4*)&KB[lane * 36 + kc * 8];
            *(float4*)&kb8[4] = *(const float4*)&KB[lane * 36 + kc * 8 + 4];
#pragma unroll
            for (int mt = 0; mt < 2; mt++)
#pragma unroll
                for (int nt = 0; nt < 4; nt++) {
                    uint32_t bb[2] = {kb8[nt * 2], kb8[nt * 2 + 1]};
                    mma_tf32(s[mt][nt], qa[mt][kc], bb);
                }
        }

        // --- mask tail keys ---
        if (k0 + 32 > len) {
#pragma unroll
            for (int nt = 0; nt < 4; nt++) {
                bool m0bad = (k0 + nt * 8 + tg) >= len;
                bool m1bad = (k0 + nt * 8 + tg + 4) >= len;
#pragma unroll
                for (int mt = 0; mt < 2; mt++) {
                    if (m0bad) { s[mt][nt][0] = NEG_INF; s[mt][nt][2] = NEG_INF; }
                    if (m1bad) { s[mt][nt][1] = NEG_INF; s[mt][nt][3] = NEG_INF; }
                }
            }
        }

        // --- online softmax (base-2), ballot-gated rescale ---
        float mn[2][2];
        bool need = false;
#pragma unroll
        for (int mt = 0; mt < 2; mt++) {
            float rlo = NEG_INF, rhi = NEG_INF;
#pragma unroll
            for (int nt = 0; nt < 4; nt++) {
                rlo = fmaxf(rlo, fmaxf(s[mt][nt][0], s[mt][nt][1]));
                rhi = fmaxf(rhi, fmaxf(s[mt][nt][2], s[mt][nt][3]));
            }
            rlo = fmaxf(rlo, __shfl_xor_sync(0xffffffffu, rlo, 1));
            rlo = fmaxf(rlo, __shfl_xor_sync(0xffffffffu, rlo, 2));
            rhi = fmaxf(rhi, __shfl_xor_sync(0xffffffffu, rhi, 1));
            rhi = fmaxf(rhi, __shfl_xor_sync(0xffffffffu, rhi, 2));
            mn[mt][0] = fmaxf(mrow[mt][0], rlo);
            mn[mt][1] = fmaxf(mrow[mt][1], rhi);
            need |= (mn[mt][0] > mrow[mt][0]) | (mn[mt][1] > mrow[mt][1]);
        }
        if (__ballot_sync(0xffffffffu, need)) {
#pragma unroll
            for (int mt = 0; mt < 2; mt++) {
                float alo = ex2f(mrow[mt][0] - mn[mt][0]);
                float ahi = ex2f(mrow[mt][1] - mn[mt][1]);
                lrow[mt][0] *= alo; lrow[mt][1] *= ahi;
#pragma unroll
                for (int dt = 0; dt < 4; dt++) {
                    o[mt][dt][0] *= alo; o[mt][dt][1] *= alo;
                    o[mt][dt][2] *= ahi; o[mt][dt][3] *= ahi;
                }
            }
        }
        mrow[0][0] = mn[0][0]; mrow[0][1] = mn[0][1];
        mrow[1][0] = mn[1][0]; mrow[1][1] = mn[1][1];

#pragma unroll
        for (int mt = 0; mt < 2; mt++) {
            float slo = 0.f, shi = 0.f;
#pragma unroll
            for (int nt = 0; nt < 4; nt++) {
                s[mt][nt][0] = ex2f(s[mt][nt][0] - mn[mt][0]);
                s[mt][nt][1] = ex2f(s[mt][nt][1] - mn[mt][0]);
                s[mt][nt][2] = ex2f(s[mt][nt][2] - mn[mt][1]);
                s[mt][nt][3] = ex2f(s[mt][nt][3] - mn[mt][1]);
                slo += s[mt][nt][0] + s[mt][nt][1];
                shi += s[mt][nt][2] + s[mt][nt][3];
            }
            slo += __shfl_xor_sync(0xffffffffu, slo, 1);
            slo += __shfl_xor_sync(0xffffffffu, slo, 2);
            shi += __shfl_xor_sync(0xffffffffu, shi, 1);
            shi += __shfl_xor_sync(0xffffffffu, shi, 2);
            lrow[mt][0] += slo; lrow[mt][1] += shi;
        }

        // --- O += P V (P already in A-layout; raw bits, no cvt) ---
#pragma unroll
        for (int kc2 = 0; kc2 < 4; kc2++) {
            uint32_t vb8[8];
            *(float4*)&vb8[0] = *(const float4*)&VB[lane * 36 + kc2 * 8];
            *(float4*)&vb8[4] = *(const float4*)&VB[lane * 36 + kc2 * 8 + 4];
#pragma unroll
            for (int mt = 0; mt < 2; mt++) {
                uint32_t pa[4] = {f2b(s[mt][kc2][0]), f2b(s[mt][kc2][2]),
                                  f2b(s[mt][kc2][1]), f2b(s[mt][kc2][3])};
#pragma unroll
                for (int dt = 0; dt < 4; dt++) {
                    uint32_t bb[2] = {vb8[dt * 2], vb8[dt * 2 + 1]};
                    mma_tf32(o[mt][dt], pa, bb);
                }
            }
        }
        __syncthreads();
    }

    // --- epilogue: normalize + store ---
#pragma unroll
    for (int mt = 0; mt < 2; mt++) {
        float ilo = 1.0f / lrow[mt][0];
        float ihi = 1.0f / lrow[mt][1];
        int r0 = qw + mt * 16 + grp, r1 = r0 + 8;
#pragma unroll
        for (int dt = 0; dt < 4; dt++) {
            int d = dt * 8 + 2 * tg;
            if (r0 < len) {
                float2 v = make_float2(o[mt][dt][0] * ilo, o[mt][dt][1] * ilo);
                *(float2*)(g_ao + (size_t)(off + r0) * D_ + h * HD_ + d) = v;
            }
            if (r1 < len) {
                float2 v = make_float2(o[mt][dt][2] * ihi, o[mt][dt][3] * ihi);
                *(float2*)(g_ao + (size_t)(off + r1) * D_ + h * HD_ + d) = v;
            }
        }
    }
}

// ---------------------------------------------------------------------------
// Launch: LN(+offsets) -> QKV GEMM -> attention -> out-proj(+residual).
// ---------------------------------------------------------------------------
extern "C" void kernel_launch(void* const* d_in, const int* in_sizes, int n_in,
                              void* d_out, int out_size) {
    const float* x     = (const float*)d_in[0];
    const float* in_w  = (const float*)d_in[1];
    const float* in_b  = (const float*)d_in[2];
    const float* out_w = (const float*)d_in[3];
    const float* out_b = (const float*)d_in[4];
    const float* gamma = (const float*)d_in[5];
    const float* beta  = (const float*)d_in[6];
    const int*   offs  = (const int*)d_in[7];

    const int T = in_sizes[0] / D_;
    const int B = in_sizes[7] - 1;
    const int Bc = (B >= 32) ? (in_sizes[7] / 2 - 1) : B;   // robust either dtype

    void *ph, *pq, *po;
    cudaGetSymbolAddress(&ph, g_h);
    cudaGetSymbolAddress(&pq, g_qkv);
    cudaGetSymbolAddress(&po, g_ao);
    float* h_ptr = (float*)ph;
    float* qkv   = (float*)pq;
    float* ao    = (float*)po;

    {   // LayerNorm + offsets canonicalization
        dim3 blk(32, 8);
        ln_kernel<<<(T + 7) / 8, blk>>>(x, gamma, beta, T, offs, Bc + 1);
    }
    {   // QKV projection: [T,256] x [768,256]^T  (tf32 tensor)
        dim3 grid((3 * D_) / 64, (T + 63) / 64);
        gemm_tf32_kernel<false><<<grid, 128>>>(h_ptr, in_w, in_b, nullptr,
                                               qkv, T, 3 * D_);
    }
    {   // tf32 mma flash attention: 128 queries per block
        dim3 grid(8, H_, Bc);
        attn_mma_kernel<<<grid, 128>>>();
    }
    {   // Output projection + residual  (tf32 tensor)
        dim3 grid(D_ / 64, (T + 63) / 64);
        gemm_tf32_kernel<true><<<grid, 128>>>(ao, out_w, out_b, x,
                                              (float*)d_out, T, D_);
    }
}

// round 6
// speedup vs baseline: 3.5068x; 1.0627x over previous
#include <cuda_runtime.h>
#include <math.h>
#include <stdint.h>

#define D_    256
#define H_    8
#define HD_   32
#define MAXT_ 16384

// Scratch (static device globals — allocation-free, within harness rules)
__device__ float g_h[(size_t)MAXT_ * D_];        // LayerNorm output      [T,256]
__device__ float g_qkv[(size_t)MAXT_ * 3 * D_];  // fused qkv projection  [T,768]
__device__ float g_ao[(size_t)MAXT_ * D_];       // attention output      [T,256]
__device__ int   g_offs[64];                     // canonical int32 batch offsets

// ---------------------------------------------------------------------------
// helpers. GEMMs use rna tf32 cvt (free on their idle ALU pipe, better
// precision). Attention feeds raw fp32 bits (rz) — its ALU pipe is hot.
// ---------------------------------------------------------------------------
__device__ __forceinline__ uint32_t f2b(float x) { return __float_as_uint(x); }
__device__ __forceinline__ uint32_t f2tf32(float x) {
    uint32_t r;
    asm("cvt.rna.tf32.f32 %0, %1;" : "=r"(r) : "f"(x));
    return r;
}
__device__ __forceinline__ float ex2f(float x) {
    float r;
    asm("ex2.approx.f32 %0, %1;" : "=f"(r) : "f"(x));
    return r;
}
__device__ __forceinline__ void mma_tf32(float c[4], const uint32_t a[4],
                                         const uint32_t b[2]) {
    asm volatile(
        "mma.sync.aligned.m16n8k8.row.col.f32.tf32.tf32.f32 "
        "{%0,%1,%2,%3}, {%4,%5,%6,%7}, {%8,%9}, {%0,%1,%2,%3};\n"
        : "+f"(c[0]), "+f"(c[1]), "+f"(c[2]), "+f"(c[3])
        : "r"(a[0]), "r"(a[1]), "r"(a[2]), "r"(a[3]), "r"(b[0]), "r"(b[1]));
}

// ---------------------------------------------------------------------------
// Kernel 1: LayerNorm (one warp per token) + offsets canonicalization.
// ---------------------------------------------------------------------------
__global__ void ln_kernel(const float* __restrict__ x,
                          const float* __restrict__ gamma,
                          const float* __restrict__ beta, int T,
                          const int* __restrict__ raw_offs, int nOffs) {
    if (blockIdx.x == 0 && threadIdx.x == 0 && threadIdx.y == 0) {
        bool is64 = (raw_offs[1] == 0);   // int64 layout: high word of offs[0]
        for (int i = 0; i < nOffs; i++)
            g_offs[i] = is64 ? raw_offs[2 * i] : raw_offs[i];
    }
    int t = blockIdx.x * blockDim.y + threadIdx.y;
    if (t >= T) return;
    int lane = threadIdx.x;
    const float* row = x + (size_t)t * D_;
    float v[8];
    float sum = 0.f, sq = 0.f;
#pragma unroll
    for (int i = 0; i < 8; i++) {
        v[i] = row[lane + i * 32];
        sum += v[i];
        sq  += v[i] * v[i];
    }
#pragma unroll
    for (int o = 16; o > 0; o >>= 1) {
        sum += __shfl_xor_sync(0xffffffffu, sum, o);
        sq  += __shfl_xor_sync(0xffffffffu, sq, o);
    }
    float mu  = sum * (1.0f / D_);
    float var = sq * (1.0f / D_) - mu * mu;
    float rs  = rsqrtf(var + 1e-5f);
    float* out = g_h + (size_t)t * D_;
#pragma unroll
    for (int i = 0; i < 8; i++) {
        int c = lane + i * 32;
        out[c] = (v[i] - mu) * rs * gamma[c] + beta[c];
    }
}

// ---------------------------------------------------------------------------
// Kernel 2/4: tf32 tensor-core GEMM  C[M,N] = A[M,K=256] @ W[N,K]^T + bias
// (+ residual). Block 128x64, BK=32, 256 threads = 8 warps (4x2),
// 32x32 per warp. Fragment-order smem (stride 36) -> LDS.128 fragment loads.
// Register-prefetch double buffering, rna tf32 conversion at staging.
// ---------------------------------------------------------------------------
template<bool RES>
__global__ __launch_bounds__(256, 2)
void gemm_tf32_kernel(const float* __restrict__ A, const float* __restrict__ W,
                      const float* __restrict__ bias, const float* __restrict__ res,
                      float* __restrict__ C, int M, int N) {
    __shared__ uint32_t AS[128 * 36];
    __shared__ uint32_t WS[64 * 36];
    const int tid  = threadIdx.x;
    const int warp = tid >> 5, lane = tid & 31;
    const int tg = lane & 3, grp = lane >> 2;
    const int wm = warp >> 1, wn = warp & 1;   // 4x2 warp grid
    const int m0 = blockIdx.y * 128, n0 = blockIdx.x * 64;

    const int lrow = tid >> 3;          // 0..31 (p-chunks add 32)
    const int lc0  = (tid & 7) * 4;     // k-column within BK
    const int lj   = lc0 >> 2;

    float4 af[4], wf[2];
#pragma unroll
    for (int p = 0; p < 4; p++) {
        int r = lrow + p * 32;
        int gr = m0 + r;
        af[p] = (gr < M) ? *(const float4*)(A + (size_t)gr * 256 + lc0)
                         : make_float4(0.f, 0.f, 0.f, 0.f);
    }
#pragma unroll
    for (int p = 0; p < 2; p++) {
        int r = lrow + p * 32;
        wf[p] = *(const float4*)(W + (size_t)(n0 + r) * 256 + lc0);
    }

    float acc[2][4][4];
#pragma unroll
    for (int mt = 0; mt < 2; mt++)
#pragma unroll
        for (int nt = 0; nt < 4; nt++)
#pragma unroll
            for (int i = 0; i < 4; i++) acc[mt][nt][i] = 0.f;

    for (int k0 = 0; k0 < 256; k0 += 32) {
        // store prefetched tile (fragment-order, rna tf32)
#pragma unroll
        for (int p = 0; p < 4; p++) {
            int r = lrow + p * 32;
            const float* ap = (const float*)&af[p];
#pragma unroll
            for (int e = 0; e < 4; e++)
                AS[r * 36 + e * 8 + lj] = f2tf32(ap[e]);
        }
#pragma unroll
        for (int p = 0; p < 2; p++) {
            int r = lrow + p * 32;
            const float* wp = (const float*)&wf[p];
#pragma unroll
            for (int e = 0; e < 4; e++)
                WS[r * 36 + e * 8 + lj] = f2tf32(wp[e]);
        }
        __syncthreads();

        if (k0 + 32 < 256) {
            int k1 = k0 + 32;
#pragma unroll
            for (int p = 0; p < 4; p++) {
                int r = lrow + p * 32;
                int gr = m0 + r;
                af[p] = (gr < M) ? *(const float4*)(A + (size_t)gr * 256 + k1 + lc0)
                                 : make_float4(0.f, 0.f, 0.f, 0.f);
            }
#pragma unroll
            for (int p = 0; p < 2; p++) {
                int r = lrow + p * 32;
                wf[p] = *(const float4*)(W + (size_t)(n0 + r) * 256 + k1 + lc0);
            }
        }

        uint32_t bR[4][8];
#pragma unroll
        for (int nt = 0; nt < 4; nt++) {
            int r = wn * 32 + nt * 8 + grp;
            *(float4*)&bR[nt][0] = *(const float4*)&WS[r * 36 + tg * 8];
            *(float4*)&bR[nt][4] = *(const float4*)&WS[r * 36 + tg * 8 + 4];
        }
#pragma unroll
        for (int mt = 0; mt < 2; mt++) {
            int r = wm * 32 + mt * 16 + grp;
            uint32_t aLo[8], aHi[8];
            *(float4*)&aLo[0] = *(const float4*)&AS[r * 36 + tg * 8];
            *(float4*)&aLo[4] = *(const float4*)&AS[r * 36 + tg * 8 + 4];
            *(float4*)&aHi[0] = *(const float4*)&AS[(r + 8) * 36 + tg * 8];
            *(float4*)&aHi[4] = *(const float4*)&AS[(r + 8) * 36 + tg * 8 + 4];
#pragma unroll
            for (int kc = 0; kc < 4; kc++) {
                uint32_t aa[4] = {aLo[2 * kc], aHi[2 * kc],
                                  aLo[2 * kc + 1], aHi[2 * kc + 1]};
#pragma unroll
                for (int nt = 0; nt < 4; nt++) {
                    uint32_t bb[2] = {bR[nt][2 * kc], bR[nt][2 * kc + 1]};
                    mma_tf32(acc[mt][nt], aa, bb);
                }
            }
        }
        __syncthreads();
    }

#pragma unroll
    for (int mt = 0; mt < 2; mt++) {
        int r0 = m0 + wm * 32 + mt * 16 + grp;
        int r1 = r0 + 8;
#pragma unroll
        for (int nt = 0; nt < 4; nt++) {
            int col = n0 + wn * 32 + nt * 8 + 2 * tg;
            float2 bv = *(const float2*)(bias + col);
            if (r0 < M) {
                float2 out = make_float2(acc[mt][nt][0] + bv.x,
                                         acc[mt][nt][1] + bv.y);
                if (RES) {
                    float2 rr = *(const float2*)(res + (size_t)r0 * N + col);
                    out.x += rr.x; out.y += rr.y;
                }
                *(float2*)(C + (size_t)r0 * N + col) = out;
            }
            if (r1 < M) {
                float2 out = make_float2(acc[mt][nt][2] + bv.x,
                                         acc[mt][nt][3] + bv.y);
                if (RES) {
                    float2 rr = *(const float2*)(res + (size_t)r1 * N + col);
                    out.x += rr.x; out.y += rr.y;
                }
                *(float2*)(C + (size_t)r1 * N + col) = out;
            }
        }
    }
}

// ---------------------------------------------------------------------------
// Kernel 3: tf32 mma.sync flash attention, v4.
// Block = 4 warps x 32 queries = 128 queries per (batch, head).
// sigma(n) = (n>>1)+(n&1)*4 key permutation: S C-layout == P A-layout (zero
// shuffles). Fragment-order smem -> LDS.128. Raw fp32 bits (no cvt).
// Ballot-gated O-rescale. l-sums kept as per-thread partials (alpha is
// quad-uniform) and reduced once in the epilogue.
// ---------------------------------------------------------------------------
__global__ __launch_bounds__(128)
void attn_mma_kernel() {
    const int b = blockIdx.z, h = blockIdx.y;
    const int off = g_offs[b];
    const int len = g_offs[b + 1] - off;
    const int q0  = blockIdx.x * 128;
    if (q0 >= len) return;

    const int tid  = threadIdx.x;
    const int warp = tid >> 5, lane = tid & 31;
    const int tg = lane & 3, grp = lane >> 2;
    const int qw = q0 + warp * 32;

    const float scale2 = 0.17677669529663687f * 1.4426950408889634f; // /sqrt(32)*log2e
    const float NEG_INF = -INFINITY;

    __shared__ uint32_t KB[32 * 36];
    __shared__ uint32_t VB[32 * 36];

    const float* qbase = g_qkv + (size_t)off * 768 + h * HD_;
    const float* kbase = qbase + D_;
    const float* vbase = qbase + 2 * D_;

    // --- Q fragments: 2 m-tiles x 4 k-chunks ---
    uint32_t qa[2][4][4];
#pragma unroll
    for (int mt = 0; mt < 2; mt++) {
        int r0 = qw + mt * 16 + grp, r1 = r0 + 8;
#pragma unroll
        for (int kc = 0; kc < 4; kc++) {
            int d0 = kc * 8 + tg, d1 = d0 + 4;
            qa[mt][kc][0] = f2b(r0 < len ? qbase[(size_t)r0 * 768 + d0] * scale2 : 0.f);
            qa[mt][kc][1] = f2b(r1 < len ? qbase[(size_t)r1 * 768 + d0] * scale2 : 0.f);
            qa[mt][kc][2] = f2b(r0 < len ? qbase[(size_t)r0 * 768 + d1] * scale2 : 0.f);
            qa[mt][kc][3] = f2b(r1 < len ? qbase[(size_t)r1 * 768 + d1] * scale2 : 0.f);
        }
    }

    float o[2][4][4];
#pragma unroll
    for (int mt = 0; mt < 2; mt++)
#pragma unroll
        for (int dt = 0; dt < 4; dt++)
#pragma unroll
            for (int i = 0; i < 4; i++) o[mt][dt][i] = 0.f;
    float mrow[2][2] = {{NEG_INF, NEG_INF}, {NEG_INF, NEG_INF}};
    float lrow[2][2] = {{0.f, 0.f}, {0.f, 0.f}};   // per-thread partials

    // loader geometry: 256 float4 slots = 32 keys x 8 d4-slots
    const int keyA = tid >> 3;
    const int keyB = (tid + 128) >> 3;
    const int d4   = (tid & 7) * 4;

    float4 kf[2], vf[2];
    {
        int keys[2] = {keyA, keyB};
#pragma unroll
        for (int p = 0; p < 2; p++) {
            bool v = keys[p] < len;
            kf[p] = v ? *(const float4*)(kbase + (size_t)keys[p] * 768 + d4)
                      : make_float4(0.f, 0.f, 0.f, 0.f);
            vf[p] = v ? *(const float4*)(vbase + (size_t)keys[p] * 768 + d4)
                      : make_float4(0.f, 0.f, 0.f, 0.f);
        }
    }

    for (int k0 = 0; k0 < len; k0 += 32) {
        // --- store prefetched K/V tile into fragment-order smem ---
        {
            int keys[2] = {keyA, keyB};
            const int kc = d4 >> 3;
            const int bq = (d4 >> 2) & 1;
            const int dt = d4 >> 3;
#pragma unroll
            for (int p = 0; p < 2; p++) {
                int key = keys[p];
                int nt = key >> 3, j = key & 7;
                int npos = (j & 3) * 2 + (j >> 2);     // sigma^-1
                int kc2 = key >> 3;
                int tgv = key & 3, bv = (key >> 2) & 1;
                const float* kp = (const float*)&kf[p];
                const float* vp = (const float*)&vf[p];
#pragma unroll
                for (int e = 0; e < 4; e++) {
                    KB[(npos * 4 + e) * 36 + kc * 8 + nt * 2 + bq] = f2b(kp[e]);
                    int gp = (d4 & 7) + e;
                    VB[(gp * 4 + tgv) * 36 + kc2 * 8 + dt * 2 + bv] = f2b(vp[e]);
                }
            }
        }
        __syncthreads();

        // --- prefetch next tile ---
        {
            int k1 = k0 + 32;
            if (k1 < len) {
                int keys[2] = {k1 + keyA, k1 + keyB};
#pragma unroll
                for (int p = 0; p < 2; p++) {
                    bool v = keys[p] < len;
                    kf[p] = v ? *(const float4*)(kbase + (size_t)keys[p] * 768 + d4)
                              : make_float4(0.f, 0.f, 0.f, 0.f);
                    vf[p] = v ? *(const float4*)(vbase + (size_t)keys[p] * 768 + d4)
                              : make_float4(0.f, 0.f, 0.f, 0.f);
                }
            }
        }

        // --- S = Q K^T ---
        float s[2][4][4];
#pragma unroll
        for (int mt = 0; mt < 2; mt++)
#pragma unroll
            for (int nt = 0; nt < 4; nt++)
#pragma unroll
                for (int i = 0; i < 4; i++) s[mt][nt][i] = 0.f;
#pragma unroll
        for (int kc = 0; kc < 4; kc++) {
            uint32_t kb8[8];
            *(float4*)&kb8[0] = *(const float4*)&KB[lane * 36 + kc * 8];
            *(float4*)&kb8[4] = *(const float4*)&KB[lane * 36 + kc * 8 + 4];
#pragma unroll
            for (int mt = 0; mt < 2; mt++)
#pragma unroll
                for (int nt = 0; nt < 4; nt++) {
                    uint32_t bb[2] = {kb8[nt * 2], kb8[nt * 2 + 1]};
                    mma_tf32(s[mt][nt], qa[mt][kc], bb);
                }
        }

        // --- mask tail keys ---
        if (k0 + 32 > len) {
#pragma unroll
            for (int nt = 0; nt < 4; nt++) {
                bool m0bad = (k0 + nt * 8 + tg) >= len;
                bool m1bad = (k0 + nt * 8 + tg + 4) >= len;
#pragma unroll
                for (int mt = 0; mt < 2; mt++) {
                    if (m0bad) { s[mt][nt][0] = NEG_INF; s[mt][nt][2] = NEG_INF; }
                    if (m1bad) { s[mt][nt][1] = NEG_INF; s[mt][nt][3] = NEG_INF; }
                }
            }
        }

        // --- online softmax (base-2), ballot-gated rescale ---
        float mn[2][2];
        bool need = false;
#pragma unroll
        for (int mt = 0; mt < 2; mt++) {
            float rlo = NEG_INF, rhi = NEG_INF;
#pragma unroll
            for (int nt = 0; nt < 4; nt++) {
                rlo = fmaxf(rlo, fmaxf(s[mt][nt][0], s[mt][nt][1]));
                rhi = fmaxf(rhi, fmaxf(s[mt][nt][2], s[mt][nt][3]));
            }
            rlo = fmaxf(rlo, __shfl_xor_sync(0xffffffffu, rlo, 1));
            rlo = fmaxf(rlo, __shfl_xor_sync(0xffffffffu, rlo, 2));
            rhi = fmaxf(rhi, __shfl_xor_sync(0xffffffffu, rhi, 1));
            rhi = fmaxf(rhi, __shfl_xor_sync(0xffffffffu, rhi, 2));
            mn[mt][0] = fmaxf(mrow[mt][0], rlo);
            mn[mt][1] = fmaxf(mrow[mt][1], rhi);
            need |= (mn[mt][0] > mrow[mt][0]) | (mn[mt][1] > mrow[mt][1]);
        }
        if (__ballot_sync(0xffffffffu, need)) {
#pragma unroll
            for (int mt = 0; mt < 2; mt++) {
                float alo = ex2f(mrow[mt][0] - mn[mt][0]);
                float ahi = ex2f(mrow[mt][1] - mn[mt][1]);
                lrow[mt][0] *= alo; lrow[mt][1] *= ahi;
#pragma unroll
                for (int dt = 0; dt < 4; dt++) {
                    o[mt][dt][0] *= alo; o[mt][dt][1] *= alo;
                    o[mt][dt][2] *= ahi; o[mt][dt][3] *= ahi;
                }
            }
        }
        mrow[0][0] = mn[0][0]; mrow[0][1] = mn[0][1];
        mrow[1][0] = mn[1][0]; mrow[1][1] = mn[1][1];

        // exp; accumulate UNreduced per-thread partial sums (reduced at end)
#pragma unroll
        for (int mt = 0; mt < 2; mt++) {
            float slo = 0.f, shi = 0.f;
#pragma unroll
            for (int nt = 0; nt < 4; nt++) {
                s[mt][nt][0] = ex2f(s[mt][nt][0] - mn[mt][0]);
                s[mt][nt][1] = ex2f(s[mt][nt][1] - mn[mt][0]);
                s[mt][nt][2] = ex2f(s[mt][nt][2] - mn[mt][1]);
                s[mt][nt][3] = ex2f(s[mt][nt][3] - mn[mt][1]);
                slo += s[mt][nt][0] + s[mt][nt][1];
                shi += s[mt][nt][2] + s[mt][nt][3];
            }
            lrow[mt][0] += slo; lrow[mt][1] += shi;
        }

        // --- O += P V (P already in A-layout; raw bits) ---
#pragma unroll
        for (int kc2 = 0; kc2 < 4; kc2++) {
            uint32_t vb8[8];
            *(float4*)&vb8[0] = *(const float4*)&VB[lane * 36 + kc2 * 8];
            *(float4*)&vb8[4] = *(const float4*)&VB[lane * 36 + kc2 * 8 + 4];
#pragma unroll
            for (int mt = 0; mt < 2; mt++) {
                uint32_t pa[4] = {f2b(s[mt][kc2][0]), f2b(s[mt][kc2][2]),
                                  f2b(s[mt][kc2][1]), f2b(s[mt][kc2][3])};
#pragma unroll
                for (int dt = 0; dt < 4; dt++) {
                    uint32_t bb[2] = {vb8[dt * 2], vb8[dt * 2 + 1]};
                    mma_tf32(o[mt][dt], pa, bb);
                }
            }
        }
        __syncthreads();
    }

    // --- epilogue: reduce l partials across quad, normalize + store ---
#pragma unroll
    for (int mt = 0; mt < 2; mt++) {
        float plo = lrow[mt][0], phi = lrow[mt][1];
        plo += __shfl_xor_sync(0xffffffffu, plo, 1);
        plo += __shfl_xor_sync(0xffffffffu, plo, 2);
        phi += __shfl_xor_sync(0xffffffffu, phi, 1);
        phi += __shfl_xor_sync(0xffffffffu, phi, 2);
        float ilo = 1.0f / plo;
        float ihi = 1.0f / phi;
        int r0 = qw + mt * 16 + grp, r1 = r0 + 8;
#pragma unroll
        for (int dt = 0; dt < 4; dt++) {
            int d = dt * 8 + 2 * tg;
            if (r0 < len) {
                float2 v = make_float2(o[mt][dt][0] * ilo, o[mt][dt][1] * ilo);
                *(float2*)(g_ao + (size_t)(off + r0) * D_ + h * HD_ + d) = v;
            }
            if (r1 < len) {
                float2 v = make_float2(o[mt][dt][2] * ihi, o[mt][dt][3] * ihi);
                *(float2*)(g_ao + (size_t)(off + r1) * D_ + h * HD_ + d) = v;
            }
        }
    }
}

// ---------------------------------------------------------------------------
// Launch: LN(+offsets) -> QKV GEMM -> attention -> out-proj(+residual).
// ---------------------------------------------------------------------------
extern "C" void kernel_launch(void* const* d_in, const int* in_sizes, int n_in,
                              void* d_out, int out_size) {
    const float* x     = (const float*)d_in[0];
    const float* in_w  = (const float*)d_in[1];
    const float* in_b  = (const float*)d_in[2];
    const float* out_w = (const float*)d_in[3];
    const float* out_b = (const float*)d_in[4];
    const float* gamma = (const float*)d_in[5];
    const float* beta  = (const float*)d_in[6];
    const int*   offs  = (const int*)d_in[7];

    const int T = in_sizes[0] / D_;
    const int B = in_sizes[7] - 1;
    const int Bc = (B >= 32) ? (in_sizes[7] / 2 - 1) : B;   // robust either dtype

    void *ph, *pq, *po;
    cudaGetSymbolAddress(&ph, g_h);
    cudaGetSymbolAddress(&pq, g_qkv);
    cudaGetSymbolAddress(&po, g_ao);
    float* h_ptr = (float*)ph;
    float* qkv   = (float*)pq;
    float* ao    = (float*)po;

    {   // LayerNorm + offsets canonicalization
        dim3 blk(32, 8);
        ln_kernel<<<(T + 7) / 8, blk>>>(x, gamma, beta, T, offs, Bc + 1);
    }
    {   // QKV projection: [T,256] x [768,256]^T  (tf32 tensor, 128x64 blocks)
        dim3 grid((3 * D_) / 64, (T + 127) / 128);
        gemm_tf32_kernel<false><<<grid, 256>>>(h_ptr, in_w, in_b, nullptr,
                                               qkv, T, 3 * D_);
    }
    {   // tf32 mma flash attention: 128 queries per block
        dim3 grid(8, H_, Bc);
        attn_mma_kernel<<<grid, 128>>>();
    }
    {   // Output projection + residual  (tf32 tensor, 128x64 blocks)
        dim3 grid(D_ / 64, (T + 127) / 128);
        gemm_tf32_kernel<true><<<grid, 256>>>(ao, out_w, out_b, x,
                                              (float*)d_out, T, D_);
    }
}